// round 3
// baseline (speedup 1.0000x reference)
#include <cuda_runtime.h>
#include <math.h>

#define D_EMB 256
#define TT    4096
#define BB    4
#define BT    (BB*TT)          // 16384 rows
#define EPSLN 1e-5f

// ---------------- scratch (static device globals: allocation-free) ----------------
__device__ float g_qkv[3L * BT * D_EMB];            // q,k,v  [3][16384][256]
__device__ float g_scores[(long)BB * TT * TT];       // [4][4096][4096]  256MB
__device__ float g_y [BT * D_EMB];                   // attn out
__device__ float g_x1[BT * D_EMB];                   // post-attn residual
__device__ float g_h [BT * 2 * D_EMB];               // ffn hidden [16384][512]
__device__ float g_y2[BT * D_EMB];                   // ffn out

// ---------------- SGEMM: C[M,N] = epi(alpha * A @ B(^T))  ----------------
// 128x128 block tile, BK=8, 256 threads, 8x8 per-thread microtile.
// All problem dims here are multiples of 128 (M,N) and 8 (K) -> no guards.
template<bool TRANSB, int EPI>   // EPI: 0 = none, 1 = leaky_relu(0.2)
__global__ __launch_bounds__(256, 2)
void sgemm(const float* __restrict__ A, const float* __restrict__ B,
           float* __restrict__ C,
           int M, int N, int K,
           long sA, long sB, long sC, float alpha)
{
    __shared__ float As[8][128];
    __shared__ float Bs[8][128];

    const int tid = threadIdx.x;
    const int tx  = tid & 15;       // 0..15  -> N microtile
    const int ty  = tid >> 4;       // 0..15  -> M microtile
    const long zb = blockIdx.z;
    A += zb * sA;  B += zb * sB;  C += zb * sC;

    const int row0 = blockIdx.y * 128;
    const int col0 = blockIdx.x * 128;

    float acc[8][8];
#pragma unroll
    for (int i = 0; i < 8; i++)
#pragma unroll
        for (int j = 0; j < 8; j++) acc[i][j] = 0.f;

    // A tile loader: 128 rows x 8 k, one float4 per thread
    const int ar = tid >> 1;          // 0..127
    const int ac = (tid & 1) * 4;     // 0 or 4
    const float* Aptr = A + (long)(row0 + ar) * K + ac;
    const float* Bptr_t = TRANSB ? (B + (long)(col0 + ar) * K + ac) : nullptr;
    const int br = tid >> 5;          // NN: 0..7 (k row)
    const int bc = (tid & 31) * 4;    // NN: 0..124

    for (int k0 = 0; k0 < K; k0 += 8) {
        float4 av = *(const float4*)(Aptr + k0);
        As[ac + 0][ar] = av.x; As[ac + 1][ar] = av.y;
        As[ac + 2][ar] = av.z; As[ac + 3][ar] = av.w;
        if (TRANSB) {
            float4 bv = *(const float4*)(Bptr_t + k0);
            Bs[ac + 0][ar] = bv.x; Bs[ac + 1][ar] = bv.y;
            Bs[ac + 2][ar] = bv.z; Bs[ac + 3][ar] = bv.w;
        } else {
            float4 bv = *(const float4*)(B + (long)(k0 + br) * N + col0 + bc);
            *(float4*)&Bs[br][bc] = bv;
        }
        __syncthreads();
#pragma unroll
        for (int k = 0; k < 8; k++) {
            float a[8], b[8];
            *(float4*)(a)     = *(const float4*)&As[k][ty * 8];
            *(float4*)(a + 4) = *(const float4*)&As[k][ty * 8 + 4];
            *(float4*)(b)     = *(const float4*)&Bs[k][tx * 8];
            *(float4*)(b + 4) = *(const float4*)&Bs[k][tx * 8 + 4];
#pragma unroll
            for (int i = 0; i < 8; i++)
#pragma unroll
                for (int j = 0; j < 8; j++)
                    acc[i][j] = fmaf(a[i], b[j], acc[i][j]);
        }
        __syncthreads();
    }

#pragma unroll
    for (int i = 0; i < 8; i++) {
        const long r = row0 + ty * 8 + i;
#pragma unroll
        for (int j = 0; j < 8; j += 4) {
            float4 v;
            v.x = alpha * acc[i][j + 0];
            v.y = alpha * acc[i][j + 1];
            v.z = alpha * acc[i][j + 2];
            v.w = alpha * acc[i][j + 3];
            if (EPI == 1) {
                v.x = v.x > 0.f ? v.x : 0.2f * v.x;
                v.y = v.y > 0.f ? v.y : 0.2f * v.y;
                v.z = v.z > 0.f ? v.z : 0.2f * v.z;
                v.w = v.w > 0.f ? v.w : 0.2f * v.w;
            }
            *(float4*)(C + r * N + col0 + tx * 8 + j) = v;
        }
    }
}

// ---------------- row softmax over T=4096, one block / row ----------------
__device__ __forceinline__ float warp_red_max(float v) {
#pragma unroll
    for (int o = 16; o; o >>= 1) v = fmaxf(v, __shfl_xor_sync(0xffffffffu, v, o));
    return v;
}
__device__ __forceinline__ float warp_red_sum(float v) {
#pragma unroll
    for (int o = 16; o; o >>= 1) v += __shfl_xor_sync(0xffffffffu, v, o);
    return v;
}

__global__ __launch_bounds__(256)
void softmax_rows(float* __restrict__ S)
{
    const long row = blockIdx.x;
    float* p = S + row * TT;
    const int tid = threadIdx.x;
    __shared__ float red[8];

    float v[16];
#pragma unroll
    for (int j = 0; j < 16; j++) v[j] = p[tid + j * 256];

    float m = -3.4e38f;
#pragma unroll
    for (int j = 0; j < 16; j++) m = fmaxf(m, v[j]);
    m = warp_red_max(m);
    if ((tid & 31) == 0) red[tid >> 5] = m;
    __syncthreads();
    m = red[0];
#pragma unroll
    for (int i = 1; i < 8; i++) m = fmaxf(m, red[i]);
    __syncthreads();

    float s = 0.f;
#pragma unroll
    for (int j = 0; j < 16; j++) { v[j] = __expf(v[j] - m); s += v[j]; }
    s = warp_red_sum(s);
    if ((tid & 31) == 0) red[tid >> 5] = s;
    __syncthreads();
    s = 0.f;
#pragma unroll
    for (int i = 0; i < 8; i++) s += red[i];
    const float inv = 1.f / s;
#pragma unroll
    for (int j = 0; j < 16; j++) p[tid + j * 256] = v[j] * inv;
}

// ---------------- warp-per-row LayerNorm helpers (D=256, 8 elems/lane) ----------------
__device__ __forceinline__ void ln_row(const float* __restrict__ in,
                                       float v[8], int lane,
                                       const float* __restrict__ w,
                                       const float* __restrict__ b)
{
#pragma unroll
    for (int j = 0; j < 8; j++) v[j] = in[lane + j * 32];
    float s = 0.f;
#pragma unroll
    for (int j = 0; j < 8; j++) s += v[j];
    const float mean = warp_red_sum(s) * (1.f / 256.f);
    float q = 0.f;
#pragma unroll
    for (int j = 0; j < 8; j++) { float d = v[j] - mean; q += d * d; }
    const float rstd = rsqrtf(warp_red_sum(q) * (1.f / 256.f) + EPSLN);
#pragma unroll
    for (int j = 0; j < 8; j++) {
        const int e = lane + j * 32;
        v[j] = (v[j] - mean) * rstd * w[e] + b[e];
    }
}

// LN(q) and LN(k) in place: gridDim.y selects tensor
__global__ __launch_bounds__(256)
void ln_qk(const float* __restrict__ wq, const float* __restrict__ bq,
           const float* __restrict__ wk, const float* __restrict__ bk)
{
    const int tensor = blockIdx.y;
    float* base = g_qkv + (long)tensor * BT * D_EMB;
    const float* w = tensor ? wk : wq;
    const float* b = tensor ? bk : bq;
    const long row = (long)blockIdx.x * 8 + (threadIdx.x >> 5);
    const int lane = threadIdx.x & 31;
    float* p = base + row * D_EMB;
    float v[8];
    ln_row(p, v, lane, w, b);
#pragma unroll
    for (int j = 0; j < 8; j++) p[lane + j * 32] = v[j];
}

// x1 = 0.7 * (x + LN(y))
__global__ __launch_bounds__(256)
void attn_ln_res(const float* __restrict__ x,
                 const float* __restrict__ w, const float* __restrict__ b)
{
    const long row = (long)blockIdx.x * 8 + (threadIdx.x >> 5);
    const int lane = threadIdx.x & 31;
    const float* py = g_y + row * D_EMB;
    const float* px = x + row * D_EMB;
    float* po = g_x1 + row * D_EMB;
    float v[8];
    ln_row(py, v, lane, w, b);
#pragma unroll
    for (int j = 0; j < 8; j++) {
        const int e = lane + j * 32;
        po[e] = 0.7f * (px[e] + v[j]);
    }
}

// out = 0.7 * (x1 + LN(y2))
__global__ __launch_bounds__(256)
void ff_ln_res(float* __restrict__ out,
               const float* __restrict__ w, const float* __restrict__ b)
{
    const long row = (long)blockIdx.x * 8 + (threadIdx.x >> 5);
    const int lane = threadIdx.x & 31;
    const float* py = g_y2 + row * D_EMB;
    const float* px = g_x1 + row * D_EMB;
    float* po = out + row * D_EMB;
    float v[8];
    ln_row(py, v, lane, w, b);
#pragma unroll
    for (int j = 0; j < 8; j++) {
        const int e = lane + j * 32;
        po[e] = 0.7f * (px[e] + v[j]);
    }
}

// ---------------- launch ----------------
extern "C" void kernel_launch(void* const* d_in, const int* in_sizes, int n_in,
                              void* d_out, int out_size)
{
    const float* x      = (const float*)d_in[0];
    const float* qkvw   = (const float*)d_in[1];
    const float* ln_q_w = (const float*)d_in[2];
    const float* ln_q_b = (const float*)d_in[3];
    const float* ln_k_w = (const float*)d_in[4];
    const float* ln_k_b = (const float*)d_in[5];
    const float* ln_a_w = (const float*)d_in[6];
    const float* ln_a_b = (const float*)d_in[7];
    const float* w1     = (const float*)d_in[8];
    const float* w2     = (const float*)d_in[9];
    const float* ln_f_w = (const float*)d_in[10];
    const float* ln_f_b = (const float*)d_in[11];
    float* out = (float*)d_out;

    float *p_qkv, *p_scores, *p_y, *p_x1, *p_h, *p_y2;
    cudaGetSymbolAddress((void**)&p_qkv,    g_qkv);
    cudaGetSymbolAddress((void**)&p_scores, g_scores);
    cudaGetSymbolAddress((void**)&p_y,      g_y);
    cudaGetSymbolAddress((void**)&p_x1,     g_x1);
    cudaGetSymbolAddress((void**)&p_h,      g_h);
    cudaGetSymbolAddress((void**)&p_y2,     g_y2);

    // 1) q,k,v = x @ qkv[n]   (NN, batch over n=0..2)
    {
        dim3 g(D_EMB / 128, BT / 128, 3);
        sgemm<false, 0><<<g, 256>>>(x, qkvw, p_qkv,
                                    BT, D_EMB, D_EMB,
                                    0L, (long)D_EMB * D_EMB, (long)BT * D_EMB, 1.f);
    }
    // 2) LN(q), LN(k) in place
    ln_qk<<<dim3(BT / 8, 2), 256>>>(ln_q_w, ln_q_b, ln_k_w, ln_k_b);

    // 3) scores = q @ k^T / 16   (NT, batch over b)
    {
        dim3 g(TT / 128, TT / 128, BB);
        sgemm<true, 0><<<g, 256>>>(p_qkv, p_qkv + (long)BT * D_EMB, p_scores,
                                   TT, TT, D_EMB,
                                   (long)TT * D_EMB, (long)TT * D_EMB, (long)TT * TT,
                                   1.f / 16.f);
    }
    // 4) softmax rows
    softmax_rows<<<BB * TT, 256>>>(p_scores);

    // 5) y = P @ v   (NN, batch over b)
    {
        dim3 g(D_EMB / 128, TT / 128, BB);
        sgemm<false, 0><<<g, 256>>>(p_scores, p_qkv + 2L * BT * D_EMB, p_y,
                                    TT, D_EMB, TT,
                                    (long)TT * TT, (long)TT * D_EMB, (long)TT * D_EMB, 1.f);
    }
    // 6) x1 = 0.7 * (x + LN(y))
    attn_ln_res<<<BT / 8, 256>>>(x, ln_a_w, ln_a_b);

    // 7) h = leaky(x1 @ w1^T)   (NT)
    {
        dim3 g(2 * D_EMB / 128, BT / 128, 1);
        sgemm<true, 1><<<g, 256>>>(p_x1, w1, p_h,
                                   BT, 2 * D_EMB, D_EMB, 0L, 0L, 0L, 1.f);
    }
    // 8) y2 = leaky(h @ w2^T)   (NT)
    {
        dim3 g(D_EMB / 128, BT / 128, 1);
        sgemm<true, 1><<<g, 256>>>(p_h, w2, p_y2,
                                   BT, D_EMB, 2 * D_EMB, 0L, 0L, 0L, 1.f);
    }
    // 9) out = 0.7 * (x1 + LN(y2))
    ff_ln_res<<<BT / 8, 256>>>(out, ln_f_w, ln_f_b);
}

// round 8
// speedup vs baseline: 2.7246x; 2.7246x over previous
#include <cuda_runtime.h>
#include <cuda_bf16.h>
#include <math.h>
#include <stdint.h>

#define D_EMB 256
#define TT    4096
#define BB    4
#define BT    (BB*TT)          // 16384 rows
#define EPSLN 1e-5f

// ---------------- scratch (static device globals: allocation-free) ----------------
__device__ float g_qkv[3L * BT * D_EMB];             // q,k,v  [3][16384][256]
__device__ float g_scores[(long)BB * TT * TT];       // [4][4096][4096]  256MB
__device__ float g_y [BT * D_EMB];                   // attn out
__device__ float g_x1[BT * D_EMB];                   // post-attn residual
__device__ float g_h [BT * 2 * D_EMB];               // ffn hidden [16384][512]
__device__ float g_y2[BT * D_EMB];                   // ffn out
__device__ float g_vT[BT * D_EMB];                   // v transposed per batch [256][4096]
__device__ float g_qkvT[3 * D_EMB * D_EMB];          // qkv weights transposed [3][D][d]

// ================= warp-MMA helpers (baseline PTX, no 'a' features) =================
__device__ __forceinline__ uint32_t smem_to_u32(const void* p) {
    uint32_t a;
    asm("{ .reg .u64 t; cvta.to.shared.u64 t, %1; cvt.u32.u64 %0, t; }" : "=r"(a) : "l"(p));
    return a;
}

#define LDMX4(r0, r1, r2, r3, addr) \
    asm volatile("ldmatrix.sync.aligned.m8n8.x4.shared.b16 {%0,%1,%2,%3}, [%4];" \
        : "=r"(r0), "=r"(r1), "=r"(r2), "=r"(r3) : "r"(addr))

#define MMA16816(c, a, b0v, b1v) \
    asm volatile("mma.sync.aligned.m16n8k16.row.col.f32.bf16.bf16.f32 " \
        "{%0,%1,%2,%3}, {%4,%5,%6,%7}, {%8,%9}, {%0,%1,%2,%3};" \
        : "+f"((c)[0]), "+f"((c)[1]), "+f"((c)[2]), "+f"((c)[3]) \
        : "r"((a)[0]), "r"((a)[1]), "r"((a)[2]), "r"((a)[3]), "r"(b0v), "r"(b1v))

// smem tiles: bf16 [128 rows][64 k], row pitch 72 bf16 = 144 B (ldmatrix conflict-free)
#define TPITCH   144
#define TILE_B   (128 * TPITCH)      // 18432 B
#define SM_AH    0
#define SM_AL    (TILE_B)
#define SM_BH    (2 * TILE_B)
#define SM_BL    (3 * TILE_B)
#define GEMM_SMEM (4 * TILE_B)       // 73728 B

// load a 128x64 fp32 tile, split into bf16 hi/lo, store to smem (pitch 144B)
__device__ __forceinline__ void load_tile_split(const float* __restrict__ g, int ld,
                                                char* sm, int hi_off, int lo_off, int tid)
{
#pragma unroll
    for (int i = 0; i < 4; i++) {
        int c  = tid + i * 256;
        int r  = c >> 3;           // 0..127
        int kc = (c & 7) * 8;      // 0..56
        const float* p = g + (long)r * ld + kc;
        float4 f0 = *(const float4*)p;
        float4 f1 = *(const float4*)(p + 4);
        float f[8] = {f0.x, f0.y, f0.z, f0.w, f1.x, f1.y, f1.z, f1.w};
        unsigned int hi[4], lo[4];
#pragma unroll
        for (int j = 0; j < 4; j++) {
            __nv_bfloat162 h = __float22bfloat162_rn(make_float2(f[2*j], f[2*j+1]));
            float r0 = f[2*j]   - __bfloat162float(h.x);
            float r1 = f[2*j+1] - __bfloat162float(h.y);
            __nv_bfloat162 l = __float22bfloat162_rn(make_float2(r0, r1));
            hi[j] = *(unsigned int*)&h;
            lo[j] = *(unsigned int*)&l;
        }
        uint32_t off = (uint32_t)(r * TPITCH + kc * 2);
        *(uint4*)(sm + hi_off + off) = make_uint4(hi[0], hi[1], hi[2], hi[3]);
        *(uint4*)(sm + lo_off + off) = make_uint4(lo[0], lo[1], lo[2], lo[3]);
    }
}

// ---------------- tensor-core GEMM: C[M,N] = epi(alpha * A[M,K] @ B[N,K]^T) ----------------
// A row-major [M,K] (lda=K), B row-major [N,K] (ldb=K), C row-major [M,N] (ldc=N).
// fp32 emulated via bf16 split: D += Ah*Bh + Al*Bh + Ah*Bl (fp32 accum in regs).
__global__ __launch_bounds__(256, 2)
void gemm_tc(const float* __restrict__ A, const float* __restrict__ B, float* __restrict__ C,
             int K, int N, long sA, long sB, long sC, float alpha, int epi)
{
    extern __shared__ char sm[];
    const uint32_t smb = smem_to_u32(sm);
    const int tid  = threadIdx.x;
    const int wid  = tid >> 5;
    const int lane = tid & 31;

    A += blockIdx.z * sA;  B += blockIdx.z * sB;  C += blockIdx.z * sC;
    const int row0 = blockIdx.y * 128;
    const int col0 = blockIdx.x * 128;

    const int m0w = (wid & 3) * 32;   // warp m offset within tile
    const int n0w = (wid >> 2) * 64;  // warp n offset within tile

    float acc[2][8][4];
#pragma unroll
    for (int m = 0; m < 2; m++)
#pragma unroll
        for (int n = 0; n < 8; n++)
#pragma unroll
            for (int j = 0; j < 4; j++) acc[m][n][j] = 0.f;

    // ldmatrix per-lane base addresses (A: rows = lane&15, k-half = lane bit4;
    // B: rows = (lane&7)+((lane&16)?8:0), k-half = lane bit3)
    const uint32_t a_base = smb + SM_AH
        + (uint32_t)((m0w + (lane & 15)) * TPITCH) + ((lane & 16) ? 16u : 0u);
    const uint32_t b_base = smb + SM_BH
        + (uint32_t)((n0w + (lane & 7) + ((lane & 16) >> 1)) * TPITCH) + ((lane & 8) ? 16u : 0u);

    const float* Ab = A + (long)row0 * K;
    const float* Bb = B + (long)col0 * K;
    const int KT = K >> 6;

    for (int kt = 0; kt < KT; kt++) {
        if (kt) __syncthreads();   // mma phase done before overwriting tiles
        load_tile_split(Ab + kt * 64, K, sm, SM_AH, SM_AL, tid);
        load_tile_split(Bb + kt * 64, K, sm, SM_BH, SM_BL, tid);
        __syncthreads();

#pragma unroll
        for (int k16 = 0; k16 < 4; k16++) {
            const uint32_t kb = (uint32_t)(k16 * 32);   // k0*2 bytes
            uint32_t ah[2][4], al[2][4];
#pragma unroll
            for (int m = 0; m < 2; m++) {
                uint32_t aa = a_base + (uint32_t)(m * 16 * TPITCH) + kb;
                LDMX4(ah[m][0], ah[m][1], ah[m][2], ah[m][3], aa);
                LDMX4(al[m][0], al[m][1], al[m][2], al[m][3], aa + TILE_B);
            }
#pragma unroll
            for (int np = 0; np < 4; np++) {
                uint32_t ba = b_base + (uint32_t)(np * 16 * TPITCH) + kb;
                uint32_t bh[4], bl[4];
                LDMX4(bh[0], bh[1], bh[2], bh[3], ba);
                LDMX4(bl[0], bl[1], bl[2], bl[3], ba + TILE_B);
#pragma unroll
                for (int m = 0; m < 2; m++) {
                    MMA16816(acc[m][np*2],   ah[m], bh[0], bh[1]);
                    MMA16816(acc[m][np*2],   al[m], bh[0], bh[1]);
                    MMA16816(acc[m][np*2],   ah[m], bl[0], bl[1]);
                    MMA16816(acc[m][np*2+1], ah[m], bh[2], bh[3]);
                    MMA16816(acc[m][np*2+1], al[m], bh[2], bh[3]);
                    MMA16816(acc[m][np*2+1], ah[m], bl[2], bl[3]);
                }
            }
        }
    }

    // epilogue: thread holds (rows r, r+8) x (2 cols) per (m-block, n-block)
#pragma unroll
    for (int m = 0; m < 2; m++) {
        const long r0 = row0 + m0w + m * 16 + (lane >> 2);
#pragma unroll
        for (int nb = 0; nb < 8; nb++) {
            const int cc = col0 + n0w + nb * 8 + (lane & 3) * 2;
            float2 v0, v1;
            v0.x = alpha * acc[m][nb][0];  v0.y = alpha * acc[m][nb][1];
            v1.x = alpha * acc[m][nb][2];  v1.y = alpha * acc[m][nb][3];
            if (epi) {
                v0.x = v0.x > 0.f ? v0.x : 0.2f * v0.x;
                v0.y = v0.y > 0.f ? v0.y : 0.2f * v0.y;
                v1.x = v1.x > 0.f ? v1.x : 0.2f * v1.x;
                v1.y = v1.y > 0.f ? v1.y : 0.2f * v1.y;
            }
            *(float2*)(C + r0 * N + cc)       = v0;
            *(float2*)(C + (r0 + 8) * N + cc) = v1;
        }
    }
}

// ---------------- tiled transpose: out[c][r] = in[r][c] ----------------
__global__ __launch_bounds__(256)
void transpose_k(const float* __restrict__ in, float* __restrict__ out,
                 int rows, int cols, long sIn, long sOut)
{
    __shared__ float t[32][33];
    in  += (long)blockIdx.z * sIn;
    out += (long)blockIdx.z * sOut;
    const int c0 = blockIdx.x * 32, r0 = blockIdx.y * 32;
    const int tx = threadIdx.x & 31, ty = threadIdx.x >> 5;   // 32 x 8
#pragma unroll
    for (int i = 0; i < 32; i += 8)
        t[ty + i][tx] = in[(long)(r0 + ty + i) * cols + c0 + tx];
    __syncthreads();
#pragma unroll
    for (int i = 0; i < 32; i += 8)
        out[(long)(c0 + ty + i) * rows + r0 + tx] = t[tx][ty + i];
}

// ---------------- row softmax over T=4096, one block / row ----------------
__device__ __forceinline__ float warp_red_max(float v) {
#pragma unroll
    for (int o = 16; o; o >>= 1) v = fmaxf(v, __shfl_xor_sync(0xffffffffu, v, o));
    return v;
}
__device__ __forceinline__ float warp_red_sum(float v) {
#pragma unroll
    for (int o = 16; o; o >>= 1) v += __shfl_xor_sync(0xffffffffu, v, o);
    return v;
}

__global__ __launch_bounds__(256)
void softmax_rows(float* __restrict__ S)
{
    const long row = blockIdx.x;
    float* p = S + row * TT;
    const int tid = threadIdx.x;
    __shared__ float red[8];

    float v[16];
#pragma unroll
    for (int j = 0; j < 16; j++) v[j] = p[tid + j * 256];

    float m = -3.4e38f;
#pragma unroll
    for (int j = 0; j < 16; j++) m = fmaxf(m, v[j]);
    m = warp_red_max(m);
    if ((tid & 31) == 0) red[tid >> 5] = m;
    __syncthreads();
    m = red[0];
#pragma unroll
    for (int i = 1; i < 8; i++) m = fmaxf(m, red[i]);
    __syncthreads();

    float s = 0.f;
#pragma unroll
    for (int j = 0; j < 16; j++) { v[j] = __expf(v[j] - m); s += v[j]; }
    s = warp_red_sum(s);
    if ((tid & 31) == 0) red[tid >> 5] = s;
    __syncthreads();
    s = 0.f;
#pragma unroll
    for (int i = 0; i < 8; i++) s += red[i];
    const float inv = 1.f / s;
#pragma unroll
    for (int j = 0; j < 16; j++) p[tid + j * 256] = v[j] * inv;
}

// ---------------- warp-per-row LayerNorm helpers (D=256, 8 elems/lane) ----------------
__device__ __forceinline__ void ln_row(const float* __restrict__ in,
                                       float v[8], int lane,
                                       const float* __restrict__ w,
                                       const float* __restrict__ b)
{
#pragma unroll
    for (int j = 0; j < 8; j++) v[j] = in[lane + j * 32];
    float s = 0.f;
#pragma unroll
    for (int j = 0; j < 8; j++) s += v[j];
    const float mean = warp_red_sum(s) * (1.f / 256.f);
    float q = 0.f;
#pragma unroll
    for (int j = 0; j < 8; j++) { float d = v[j] - mean; q += d * d; }
    const float rstd = rsqrtf(warp_red_sum(q) * (1.f / 256.f) + EPSLN);
#pragma unroll
    for (int j = 0; j < 8; j++) {
        const int e = lane + j * 32;
        v[j] = (v[j] - mean) * rstd * w[e] + b[e];
    }
}

__global__ __launch_bounds__(256)
void ln_qk(const float* __restrict__ wq, const float* __restrict__ bq,
           const float* __restrict__ wk, const float* __restrict__ bk)
{
    const int tensor = blockIdx.y;
    float* base = g_qkv + (long)tensor * BT * D_EMB;
    const float* w = tensor ? wk : wq;
    const float* b = tensor ? bk : bq;
    const long row = (long)blockIdx.x * 8 + (threadIdx.x >> 5);
    const int lane = threadIdx.x & 31;
    float* p = base + row * D_EMB;
    float v[8];
    ln_row(p, v, lane, w, b);
#pragma unroll
    for (int j = 0; j < 8; j++) p[lane + j * 32] = v[j];
}

__global__ __launch_bounds__(256)
void attn_ln_res(const float* __restrict__ x,
                 const float* __restrict__ w, const float* __restrict__ b)
{
    const long row = (long)blockIdx.x * 8 + (threadIdx.x >> 5);
    const int lane = threadIdx.x & 31;
    const float* py = g_y + row * D_EMB;
    const float* px = x + row * D_EMB;
    float* po = g_x1 + row * D_EMB;
    float v[8];
    ln_row(py, v, lane, w, b);
#pragma unroll
    for (int j = 0; j < 8; j++) {
        const int e = lane + j * 32;
        po[e] = 0.7f * (px[e] + v[j]);
    }
}

__global__ __launch_bounds__(256)
void ff_ln_res(float* __restrict__ out,
               const float* __restrict__ w, const float* __restrict__ b)
{
    const long row = (long)blockIdx.x * 8 + (threadIdx.x >> 5);
    const int lane = threadIdx.x & 31;
    const float* py = g_y2 + row * D_EMB;
    const float* px = g_x1 + row * D_EMB;
    float* po = out + row * D_EMB;
    float v[8];
    ln_row(py, v, lane, w, b);
#pragma unroll
    for (int j = 0; j < 8; j++) {
        const int e = lane + j * 32;
        po[e] = 0.7f * (px[e] + v[j]);
    }
}

// ---------------- launch ----------------
extern "C" void kernel_launch(void* const* d_in, const int* in_sizes, int n_in,
                              void* d_out, int out_size)
{
    const float* x      = (const float*)d_in[0];
    const float* qkvw   = (const float*)d_in[1];
    const float* ln_q_w = (const float*)d_in[2];
    const float* ln_q_b = (const float*)d_in[3];
    const float* ln_k_w = (const float*)d_in[4];
    const float* ln_k_b = (const float*)d_in[5];
    const float* ln_a_w = (const float*)d_in[6];
    const float* ln_a_b = (const float*)d_in[7];
    const float* w1     = (const float*)d_in[8];
    const float* w2     = (const float*)d_in[9];
    const float* ln_f_w = (const float*)d_in[10];
    const float* ln_f_b = (const float*)d_in[11];
    float* out = (float*)d_out;

    float *p_qkv, *p_scores, *p_y, *p_x1, *p_h, *p_y2, *p_vT, *p_qkvT;
    cudaGetSymbolAddress((void**)&p_qkv,    g_qkv);
    cudaGetSymbolAddress((void**)&p_scores, g_scores);
    cudaGetSymbolAddress((void**)&p_y,      g_y);
    cudaGetSymbolAddress((void**)&p_x1,     g_x1);
    cudaGetSymbolAddress((void**)&p_h,      g_h);
    cudaGetSymbolAddress((void**)&p_y2,     g_y2);
    cudaGetSymbolAddress((void**)&p_vT,     g_vT);
    cudaGetSymbolAddress((void**)&p_qkvT,   g_qkvT);

    cudaFuncSetAttribute(gemm_tc, cudaFuncAttributeMaxDynamicSharedMemorySize, GEMM_SMEM);

    // 0) transpose qkv weights: [3][d][D] -> [3][D][d]  (so every GEMM is NT)
    transpose_k<<<dim3(8, 8, 3), 256>>>(qkvw, p_qkvT, 256, 256,
                                        (long)D_EMB * D_EMB, (long)D_EMB * D_EMB);

    // 1) q,k,v = x @ qkvT[n]^T   M=16384, N=256, K=256
    gemm_tc<<<dim3(2, 128, 3), 256, GEMM_SMEM>>>(
        x, p_qkvT, p_qkv, D_EMB, D_EMB,
        0L, (long)D_EMB * D_EMB, (long)BT * D_EMB, 1.f, 0);

    // 2) transpose v (per batch): [4096][256] -> [256][4096]
    transpose_k<<<dim3(8, 128, BB), 256>>>(p_qkv + 2L * BT * D_EMB, p_vT,
                                           TT, D_EMB, (long)TT * D_EMB, (long)TT * D_EMB);

    // 3) LN(q), LN(k) in place
    ln_qk<<<dim3(BT / 8, 2), 256>>>(ln_q_w, ln_q_b, ln_k_w, ln_k_b);

    // 4) scores = q @ k^T / 16   M=N=4096, K=256 per batch
    gemm_tc<<<dim3(32, 32, BB), 256, GEMM_SMEM>>>(
        p_qkv, p_qkv + (long)BT * D_EMB, p_scores, D_EMB, TT,
        (long)TT * D_EMB, (long)TT * D_EMB, (long)TT * TT, 1.f / 16.f, 0);

    // 5) softmax rows
    softmax_rows<<<BB * TT, 256>>>(p_scores);

    // 6) y = P @ vT^T   M=4096, N=256, K=4096 per batch
    gemm_tc<<<dim3(2, 32, BB), 256, GEMM_SMEM>>>(
        p_scores, p_vT, p_y, TT, D_EMB,
        (long)TT * TT, (long)D_EMB * TT, (long)TT * D_EMB, 1.f, 0);

    // 7) x1 = 0.7 * (x + LN(y))
    attn_ln_res<<<BT / 8, 256>>>(x, ln_a_w, ln_a_b);

    // 8) h = leaky(x1 @ w1^T)   M=16384, N=512, K=256
    gemm_tc<<<dim3(4, 128, 1), 256, GEMM_SMEM>>>(
        p_x1, w1, p_h, D_EMB, 2 * D_EMB, 0L, 0L, 0L, 1.f, 1);

    // 9) y2 = leaky(h @ w2^T)   M=16384, N=256, K=512
    gemm_tc<<<dim3(2, 128, 1), 256, GEMM_SMEM>>>(
        p_h, w2, p_y2, 2 * D_EMB, D_EMB, 0L, 0L, 0L, 1.f, 1);

    // 10) out = 0.7 * (x1 + LN(y2))
    ff_ln_res<<<BT / 8, 256>>>(out, ln_f_w, ln_f_b);
}